// round 15
// baseline (speedup 1.0000x reference)
#include <cuda_runtime.h>

#define N_REF   50000
#define Q_NUM   4096
#define TN      339                 // refs per smem tile
#define NTILES  148                 // 339*148 = 50172 >= 50000
#define BLOCK   256
#define QPT     8                   // queries per thread (4 f32x2 pairs)
#define NPAIR   (QPT / 2)           // 4
#define QTILE   (BLOCK * QPT)       // 2048
#define QTILES  (Q_NUM / QTILE)     // 2 -> 2*148 = 296 blocks = 148 SMs * 2

typedef unsigned long long u64;
typedef unsigned int u32;

// accumulators: [plane][q], plane 0=w, 1=lx, 2=ly. Static zero-init; the
// finisher block resets them after consuming -> graph-replay safe.
__device__ float g_accum[3][Q_NUM];
// per-qtile completion counters (reset by finisher)
__device__ u32 g_count[QTILES];

// ---------------- f32x2 helpers (Blackwell packed fp32) ----------------
__device__ __forceinline__ u64 fma2(u64 a, u64 b, u64 c) {
    u64 d;
    asm("fma.rn.f32x2 %0, %1, %2, %3;" : "=l"(d) : "l"(a), "l"(b), "l"(c));
    return d;
}
__device__ __forceinline__ u64 add2(u64 a, u64 b) {
    u64 d;
    asm("add.rn.f32x2 %0, %1, %2;" : "=l"(d) : "l"(a), "l"(b));
    return d;
}
__device__ __forceinline__ u64 pack2(float lo, float hi) {
    u64 d;
    asm("mov.b64 %0, {%1, %2};" : "=l"(d) : "f"(lo), "f"(hi));
    return d;
}
__device__ __forceinline__ void unpack2(u64 v, float& lo, float& hi) {
    asm("mov.b64 {%0, %1}, %2;" : "=f"(lo), "=f"(hi) : "l"(v));
}
// raw MUFU.EX2 — exp2 with ~2^-22 rel err, FTZ (ex2(-1e30) -> +0)
__device__ __forceinline__ float ex2(float x) {
    float y;
    asm("ex2.approx.ftz.f32 %0, %1;" : "=f"(y) : "f"(x));
    return y;
}

// ---------------- single fused kernel ------------------------------------
// smem per ref (16 floats / 64B):
// {r0,r0,r1,r1,r2,r2,r3,r3,r4,r4,rbar,rbar,l0,l0,l1,l1}, rbar = -k*|r|^2,
// k = log2(e)/(2 sigma^2). w = exp2(rbar + sum_d xs_d*r_d), xs_d = x_d*2k;
// the per-query factor exp2(-k*|x|^2) cancels in the normalization.
// Inner loop = R8/R12/R14 best-measured shape. Epilogue: atomicAdd into
// g_accum; the LAST block of each qtile (completion counter) normalizes,
// writes out, and resets state (no second kernel launch).
__global__ __launch_bounds__(BLOCK, 2)
void sknn_main_kernel(const float* __restrict__ rss,
                      const float* __restrict__ Radio,
                      const float* __restrict__ Loc,
                      const float* __restrict__ sigma,
                      float* __restrict__ out) {
    __shared__ u64 sh[TN * 8];  // 21.7 KB
    __shared__ u32 s_last;

    const u32 qtile = blockIdx.x;   // 0..1
    const u32 ntile = blockIdx.y;   // 0..147
    const u32 t     = threadIdx.x;

    const float s  = sigma[0];
    const float k  = 0.5f * 1.4426950408889634f / (s * s);
    const float k2 = 2.0f * k;

    // ---- pack this block's ref tile directly into smem ----
    for (u32 i = t; i < TN; i += BLOCK) {
        const u32 n = ntile * TN + i;
        float o[16];
        if (n < N_REF) {
            float r2 = 0.0f;
#pragma unroll
            for (int d = 0; d < 5; d++) {
                float r = Radio[n * 5 + d];
                o[2 * d] = r;
                o[2 * d + 1] = r;
                r2 = fmaf(r, r, r2);
            }
            float rbar = -k * r2;
            o[10] = rbar; o[11] = rbar;
            float l0 = Loc[n * 2 + 0], l1 = Loc[n * 2 + 1];
            o[12] = l0; o[13] = l0;
            o[14] = l1; o[15] = l1;
        } else {
#pragma unroll
            for (int j = 0; j < 16; j++) o[j] = 0.0f;
            o[10] = -1e30f; o[11] = -1e30f;   // ex2 -> +0: contributes nothing
        }
        float4* dst = reinterpret_cast<float4*>(sh + i * 8);
        const float4* src = reinterpret_cast<const float4*>(o);
        dst[0] = src[0]; dst[1] = src[1]; dst[2] = src[2]; dst[3] = src[3];
    }

    // ---- 8 queries per thread as 4 f32x2 pairs ----
    // pair p holds queries q0 + (2p)*BLOCK and q0 + (2p+1)*BLOCK
    const u32 q0 = qtile * QTILE + t;
    u64 xs[NPAIR][5];
#pragma unroll
    for (int p = 0; p < NPAIR; p++) {
#pragma unroll
        for (int d = 0; d < 5; d++) {
            float a = rss[(q0 + (2 * p + 0) * BLOCK) * 5 + d] * k2;
            float b = rss[(q0 + (2 * p + 1) * BLOCK) * 5 + d] * k2;
            xs[p][d] = pack2(a, b);
        }
    }
    __syncthreads();

    u64 wsum[NPAIR], lx[NPAIR], ly[NPAIR];
    u64 evp[NPAIR];                   // pipelined ev from previous iter
    u64 lp0 = 0ull, lp1 = 0ull;       // previous iter's loc values
#pragma unroll
    for (int p = 0; p < NPAIR; p++) {
        wsum[p] = 0ull; lx[p] = 0ull; ly[p] = 0ull; evp[p] = 0ull;
    }

    // register double-buffer: preload ref 0
    const ulonglong2* eptr = reinterpret_cast<const ulonglong2*>(sh);
    ulonglong2 v0 = eptr[0], v1 = eptr[1], v2 = eptr[2], v3 = eptr[3];

#pragma unroll 1
    for (u32 i = 0; i < TN; i++) {
        const u64 r0 = v0.x, r1 = v0.y, r2 = v1.x, r3 = v1.y;
        const u64 r4 = v2.x, rb = v2.y, l0 = v3.x, l1 = v3.y;

        // prefetch next ref (overlaps the whole body below)
        if (i + 1 < TN) {
            const ulonglong2* nx = eptr + (i + 1) * 4;
            v0 = nx[0]; v1 = nx[1]; v2 = nx[2]; v3 = nx[3];
        }

        // breadth-first FMA chains (4 independent)
        u64 acc[NPAIR];
#pragma unroll
        for (int p = 0; p < NPAIR; p++) acc[p] = fma2(xs[p][0], r0, rb);
#pragma unroll
        for (int p = 0; p < NPAIR; p++) acc[p] = fma2(xs[p][1], r1, acc[p]);
#pragma unroll
        for (int p = 0; p < NPAIR; p++) acc[p] = fma2(xs[p][2], r2, acc[p]);

        // accumulate PREVIOUS iteration's ev (MUFU results long ready)
#pragma unroll
        for (int p = 0; p < NPAIR; p++) {
            wsum[p] = add2(wsum[p], evp[p]);
            lx[p]   = fma2(evp[p], lp0, lx[p]);
            ly[p]   = fma2(evp[p], lp1, ly[p]);
        }

#pragma unroll
        for (int p = 0; p < NPAIR; p++) acc[p] = fma2(xs[p][3], r3, acc[p]);
#pragma unroll
        for (int p = 0; p < NPAIR; p++) acc[p] = fma2(xs[p][4], r4, acc[p]);

        // issue this iteration's EX2s; consumed next iteration
#pragma unroll
        for (int p = 0; p < NPAIR; p++) {
            float alo, ahi;
            unpack2(acc[p], alo, ahi);
            evp[p] = pack2(ex2(alo), ex2(ahi));
        }
        lp0 = l0; lp1 = l1;
    }
    // drain the pipeline
#pragma unroll
    for (int p = 0; p < NPAIR; p++) {
        wsum[p] = add2(wsum[p], evp[p]);
        lx[p]   = fma2(evp[p], lp0, lx[p]);
        ly[p]   = fma2(evp[p], lp1, ly[p]);
    }

    // ---- combine across blocks: spread-address float atomics ----
#pragma unroll
    for (int p = 0; p < NPAIR; p++) {
        float w0, w1, x0, x1, y0, y1;
        unpack2(wsum[p], w0, w1);
        unpack2(lx[p],   x0, x1);
        unpack2(ly[p],   y0, y1);
        u32 qa = q0 + (2 * p + 0) * BLOCK;
        u32 qb = q0 + (2 * p + 1) * BLOCK;
        atomicAdd(&g_accum[0][qa], w0);
        atomicAdd(&g_accum[1][qa], x0);
        atomicAdd(&g_accum[2][qa], y0);
        atomicAdd(&g_accum[0][qb], w1);
        atomicAdd(&g_accum[1][qb], x1);
        atomicAdd(&g_accum[2][qb], y1);
    }

    // ---- last-block finisher: normalize + write out + reset -------------
    __threadfence();   // release: my atomics visible before counter bump
    if (t == 0) {
        u32 prev = atomicAdd(&g_count[qtile], 1u);
        s_last = (prev == NTILES - 1) ? 1u : 0u;
    }
    __syncthreads();
    if (s_last == 0u) return;
    __threadfence();   // acquire: all qtile contributions now visible

    // this block finalizes its qtile's 2048 queries: 256 thr x 8 q each
#pragma unroll
    for (int p = 0; p < QPT; p++) {
        const u32 q = qtile * QTILE + t + p * BLOCK;
        float w = __ldcg(&g_accum[0][q]);
        float x = __ldcg(&g_accum[1][q]);
        float y = __ldcg(&g_accum[2][q]);
        float inv = 1.0f / w;
        out[q * 2 + 0] = x * inv;
        out[q * 2 + 1] = y * inv;
        // reset for the next launch / graph replay
        g_accum[0][q] = 0.0f;
        g_accum[1][q] = 0.0f;
        g_accum[2][q] = 0.0f;
    }
    __threadfence();   // accum resets visible before counter reset
    __syncthreads();
    if (t == 0) atomicExch(&g_count[qtile], 0u);
}

// ---------------- launch -------------------------------------------------
extern "C" void kernel_launch(void* const* d_in, const int* in_sizes, int n_in,
                              void* d_out, int out_size) {
    (void)in_sizes; (void)n_in; (void)out_size;
    const float* rss   = (const float*)d_in[0];  // [4096, 5]
    const float* Radio = (const float*)d_in[1];  // [50000, 5]
    const float* Loc   = (const float*)d_in[2];  // [50000, 2]
    const float* sigma = (const float*)d_in[3];  // [1]
    float* out = (float*)d_out;                  // [4096, 2]

    dim3 grid(QTILES, NTILES);
    sknn_main_kernel<<<grid, BLOCK>>>(rss, Radio, Loc, sigma, out);
}

// round 16
// speedup vs baseline: 1.1838x; 1.1838x over previous
#include <cuda_runtime.h>

#define N_REF   50000
#define Q_NUM   4096
#define TN      339                 // refs per smem tile
#define NTILES  148                 // 339*148 = 50172 >= 50000
#define BLOCK   256
#define QPT     8                   // queries per thread (4 f32x2 pairs)
#define NPAIR   (QPT / 2)           // 4
#define QTILE   (BLOCK * QPT)       // 2048
#define QTILES  (Q_NUM / QTILE)     // 2 -> 2*148 = 296 blocks = 148 SMs * 2

typedef unsigned long long u64;
typedef unsigned int u32;

// accumulators: [plane][q], plane 0=w, 1=lx, 2=ly. Static zero-init; the
// divide kernel resets them to zero after consuming -> graph-replay safe.
__device__ float g_accum[3][Q_NUM];

// ---------------- f32x2 helpers (Blackwell packed fp32) ----------------
__device__ __forceinline__ u64 fma2(u64 a, u64 b, u64 c) {
    u64 d;
    asm("fma.rn.f32x2 %0, %1, %2, %3;" : "=l"(d) : "l"(a), "l"(b), "l"(c));
    return d;
}
__device__ __forceinline__ u64 add2(u64 a, u64 b) {
    u64 d;
    asm("add.rn.f32x2 %0, %1, %2;" : "=l"(d) : "l"(a), "l"(b));
    return d;
}
__device__ __forceinline__ u64 pack2(float lo, float hi) {
    u64 d;
    asm("mov.b64 %0, {%1, %2};" : "=l"(d) : "f"(lo), "f"(hi));
    return d;
}
__device__ __forceinline__ void unpack2(u64 v, float& lo, float& hi) {
    asm("mov.b64 {%0, %1}, %2;" : "=f"(lo), "=f"(hi) : "l"(v));
}
// raw MUFU.EX2 — exp2 with ~2^-22 rel err, FTZ (ex2(-1e30) -> +0)
__device__ __forceinline__ float ex2(float x) {
    float y;
    asm("ex2.approx.ftz.f32 %0, %1;" : "=f"(y) : "f"(x));
    return y;
}

// ---------------- main: fused pack + partial sums + atomic combine ------
// smem per ref (16 floats / 64B):
// {r0,r0,r1,r1,r2,r2,r3,r3,r4,r4,rbar,rbar,l0,l0,l1,l1}, rbar = -k*|r|^2,
// k = log2(e)/(2 sigma^2). w = exp2(rbar + sum_d xs_d*r_d), xs_d = x_d*2k;
// the per-query factor exp2(-k*|x|^2) cancels in the normalization.
// Inner loop = R8/R12/R14 best-measured shape (UNTOUCHED). Epilogue:
// atomicAdd into g_accum, then a single griddepcontrol.launch_dependents
// so the PDL-attributed divide kernel overlaps this kernel's drain.
__global__ __launch_bounds__(BLOCK, 2)
void sknn_main_kernel(const float* __restrict__ rss,
                      const float* __restrict__ Radio,
                      const float* __restrict__ Loc,
                      const float* __restrict__ sigma) {
    __shared__ u64 sh[TN * 8];  // 21.7 KB

    const u32 qtile = blockIdx.x;   // 0..1
    const u32 ntile = blockIdx.y;   // 0..147
    const u32 t     = threadIdx.x;

    const float s  = sigma[0];
    const float k  = 0.5f * 1.4426950408889634f / (s * s);
    const float k2 = 2.0f * k;

    // ---- pack this block's ref tile directly into smem ----
    for (u32 i = t; i < TN; i += BLOCK) {
        const u32 n = ntile * TN + i;
        float o[16];
        if (n < N_REF) {
            float r2 = 0.0f;
#pragma unroll
            for (int d = 0; d < 5; d++) {
                float r = Radio[n * 5 + d];
                o[2 * d] = r;
                o[2 * d + 1] = r;
                r2 = fmaf(r, r, r2);
            }
            float rbar = -k * r2;
            o[10] = rbar; o[11] = rbar;
            float l0 = Loc[n * 2 + 0], l1 = Loc[n * 2 + 1];
            o[12] = l0; o[13] = l0;
            o[14] = l1; o[15] = l1;
        } else {
#pragma unroll
            for (int j = 0; j < 16; j++) o[j] = 0.0f;
            o[10] = -1e30f; o[11] = -1e30f;   // ex2 -> +0: contributes nothing
        }
        float4* dst = reinterpret_cast<float4*>(sh + i * 8);
        const float4* src = reinterpret_cast<const float4*>(o);
        dst[0] = src[0]; dst[1] = src[1]; dst[2] = src[2]; dst[3] = src[3];
    }

    // ---- 8 queries per thread as 4 f32x2 pairs ----
    // pair p holds queries q0 + (2p)*BLOCK and q0 + (2p+1)*BLOCK
    const u32 q0 = qtile * QTILE + t;
    u64 xs[NPAIR][5];
#pragma unroll
    for (int p = 0; p < NPAIR; p++) {
#pragma unroll
        for (int d = 0; d < 5; d++) {
            float a = rss[(q0 + (2 * p + 0) * BLOCK) * 5 + d] * k2;
            float b = rss[(q0 + (2 * p + 1) * BLOCK) * 5 + d] * k2;
            xs[p][d] = pack2(a, b);
        }
    }
    __syncthreads();

    u64 wsum[NPAIR], lx[NPAIR], ly[NPAIR];
    u64 evp[NPAIR];                   // pipelined ev from previous iter
    u64 lp0 = 0ull, lp1 = 0ull;       // previous iter's loc values
#pragma unroll
    for (int p = 0; p < NPAIR; p++) {
        wsum[p] = 0ull; lx[p] = 0ull; ly[p] = 0ull; evp[p] = 0ull;
    }

    // register double-buffer: preload ref 0
    const ulonglong2* eptr = reinterpret_cast<const ulonglong2*>(sh);
    ulonglong2 v0 = eptr[0], v1 = eptr[1], v2 = eptr[2], v3 = eptr[3];

#pragma unroll 1
    for (u32 i = 0; i < TN; i++) {
        const u64 r0 = v0.x, r1 = v0.y, r2 = v1.x, r3 = v1.y;
        const u64 r4 = v2.x, rb = v2.y, l0 = v3.x, l1 = v3.y;

        // prefetch next ref (overlaps the whole body below)
        if (i + 1 < TN) {
            const ulonglong2* nx = eptr + (i + 1) * 4;
            v0 = nx[0]; v1 = nx[1]; v2 = nx[2]; v3 = nx[3];
        }

        // breadth-first FMA chains (4 independent)
        u64 acc[NPAIR];
#pragma unroll
        for (int p = 0; p < NPAIR; p++) acc[p] = fma2(xs[p][0], r0, rb);
#pragma unroll
        for (int p = 0; p < NPAIR; p++) acc[p] = fma2(xs[p][1], r1, acc[p]);
#pragma unroll
        for (int p = 0; p < NPAIR; p++) acc[p] = fma2(xs[p][2], r2, acc[p]);

        // accumulate PREVIOUS iteration's ev (MUFU results long ready)
#pragma unroll
        for (int p = 0; p < NPAIR; p++) {
            wsum[p] = add2(wsum[p], evp[p]);
            lx[p]   = fma2(evp[p], lp0, lx[p]);
            ly[p]   = fma2(evp[p], lp1, ly[p]);
        }

#pragma unroll
        for (int p = 0; p < NPAIR; p++) acc[p] = fma2(xs[p][3], r3, acc[p]);
#pragma unroll
        for (int p = 0; p < NPAIR; p++) acc[p] = fma2(xs[p][4], r4, acc[p]);

        // issue this iteration's EX2s; consumed next iteration
#pragma unroll
        for (int p = 0; p < NPAIR; p++) {
            float alo, ahi;
            unpack2(acc[p], alo, ahi);
            evp[p] = pack2(ex2(alo), ex2(ahi));
        }
        lp0 = l0; lp1 = l1;
    }
    // drain the pipeline
#pragma unroll
    for (int p = 0; p < NPAIR; p++) {
        wsum[p] = add2(wsum[p], evp[p]);
        lx[p]   = fma2(evp[p], lp0, lx[p]);
        ly[p]   = fma2(evp[p], lp1, ly[p]);
    }

    // ---- combine across blocks: spread-address float atomics ----
    // Consecutive threads hit consecutive q -> distinct addresses (no
    // serialization); 148 blocks per address arrive spread over ~60us.
#pragma unroll
    for (int p = 0; p < NPAIR; p++) {
        float w0, w1, x0, x1, y0, y1;
        unpack2(wsum[p], w0, w1);
        unpack2(lx[p],   x0, x1);
        unpack2(ly[p],   y0, y1);
        u32 qa = q0 + (2 * p + 0) * BLOCK;
        u32 qb = q0 + (2 * p + 1) * BLOCK;
        atomicAdd(&g_accum[0][qa], w0);
        atomicAdd(&g_accum[1][qa], x0);
        atomicAdd(&g_accum[2][qa], y0);
        atomicAdd(&g_accum[0][qb], w1);
        atomicAdd(&g_accum[1][qb], x1);
        atomicAdd(&g_accum[2][qb], y1);
    }

    // PDL: allow the dependent (divide) grid to launch as blocks drain.
    // Atomics above precede this in program order -> visible to the
    // dependent after its griddepcontrol.wait.
    asm volatile("griddepcontrol.launch_dependents;");
}

// ---- normalize + reset (PDL dependent; resets make replay-safe) ---------
__global__ __launch_bounds__(256)
void sknn_divide_kernel(float* __restrict__ out) {
    // wait for the primary grid's memory to be visible
    asm volatile("griddepcontrol.wait;" ::: "memory");
    const u32 q = blockIdx.x * blockDim.x + threadIdx.x;
    if (q >= Q_NUM) return;
    float w = g_accum[0][q];
    float x = g_accum[1][q];
    float y = g_accum[2][q];
    float inv = 1.0f / w;
    out[q * 2 + 0] = x * inv;
    out[q * 2 + 1] = y * inv;
    // reset for the next kernel_launch invocation / graph replay
    g_accum[0][q] = 0.0f;
    g_accum[1][q] = 0.0f;
    g_accum[2][q] = 0.0f;
}

// ---------------- launch -------------------------------------------------
extern "C" void kernel_launch(void* const* d_in, const int* in_sizes, int n_in,
                              void* d_out, int out_size) {
    (void)in_sizes; (void)n_in; (void)out_size;
    const float* rss   = (const float*)d_in[0];  // [4096, 5]
    const float* Radio = (const float*)d_in[1];  // [50000, 5]
    const float* Loc   = (const float*)d_in[2];  // [50000, 2]
    const float* sigma = (const float*)d_in[3];  // [1]
    float* out = (float*)d_out;                  // [4096, 2]

    dim3 grid(QTILES, NTILES);
    sknn_main_kernel<<<grid, BLOCK>>>(rss, Radio, Loc, sigma);

    // divide kernel with programmatic dependent launch: overlaps main's tail
    cudaLaunchConfig_t cfg = {};
    cfg.gridDim  = dim3(Q_NUM / 256);
    cfg.blockDim = dim3(256);
    cfg.dynamicSmemBytes = 0;
    cfg.stream = 0;   // same (capture) stream as the <<<>>> launch above
    cudaLaunchAttribute attrs[1];
    attrs[0].id = cudaLaunchAttributeProgrammaticStreamSerialization;
    attrs[0].val.programmaticStreamSerializationAllowed = 1;
    cfg.attrs = attrs;
    cfg.numAttrs = 1;
    cudaLaunchKernelEx(&cfg, sknn_divide_kernel, out);
}